// round 10
// baseline (speedup 1.0000x reference)
#include <cuda_runtime.h>
#include <cuda_fp16.h>
#include <cuda_bf16.h>
#include <mma.h>
#include <math.h>

using namespace nvcuda;

#define N_NODES 50000
#define N_EDGES 1600000
#define IN_F    256
#define OUT_F   128
#define ALPHA   0.2f
#define EPSV    1e-9f

// GEMM tiling: 128x128 block tile, BK=16, double-buffered smem
#define GBM 128
#define GBN 128
#define GBK 16
#define N_PAD 50048   // 391 blocks * 128 rows

// scan config
#define SCAN_BS 256
#define SCAN_NB ((N_NODES + SCAN_BS - 1) / SCAN_BS)   // 196

// ---------------- scratch (device globals; no allocations allowed) ----------
__device__ __half g_hh[(size_t)N_PAD * OUT_F];
__device__ float  g_ssrc[N_PAD];
__device__ float  g_sdst[N_PAD];
__device__ int    g_deg[N_NODES];
__device__ int    g_off[N_NODES + 1];
__device__ int    g_cursor[N_NODES];
__device__ int    g_part[SCAN_NB];
__device__ int2   g_edge[N_EDGES];    // packed (dst, w bits)

// ---------------- GEMM: h = x @ W (tf32) + fused fp16 store + scores --------
__global__ __launch_bounds__(256) void gemm_tf32_fused_kernel(
    const float* __restrict__ x, const float* __restrict__ W,
    const float* __restrict__ a,
    __half* __restrict__ hh, float* __restrict__ ssrc, float* __restrict__ sdst,
    int N)
{
    __shared__ float As[2][GBM][GBK + 4];   // 20.5 KB (reused as epilogue stage)
    __shared__ float Bs[2][GBK][GBN];       // 16 KB

    const int tid = threadIdx.x;
    const int wid = tid >> 5;
    const int lane = tid & 31;
    const int wm = wid >> 2;       // 0..1 -> 64 rows each
    const int wn = wid & 3;        // 0..3 -> 32 cols each
    const int row0 = blockIdx.x * GBM;

    const int ar0 = tid >> 2;
    const int ac  = (tid & 3) * 4;
    const int br0 = tid >> 5;
    const int bc  = (tid & 31) * 4;

    wmma::fragment<wmma::accumulator, 16, 16, 8, float> acc[4][2];
#pragma unroll
    for (int i = 0; i < 4; i++)
#pragma unroll
        for (int j = 0; j < 2; j++) wmma::fill_fragment(acc[i][j], 0.f);

    // preload chunk 0 into buffer 0
#pragma unroll
    for (int i = 0; i < 2; i++) {
        int grow = row0 + ar0 + i * 64; if (grow >= N) grow = N - 1;
        *reinterpret_cast<float4*>(&As[0][ar0 + i * 64][ac]) =
            *reinterpret_cast<const float4*>(x + (size_t)grow * IN_F + ac);
        *reinterpret_cast<float4*>(&Bs[0][br0 + i * 8][bc]) =
            *reinterpret_cast<const float4*>(W + (size_t)(br0 + i * 8) * GBN + bc);
    }
    __syncthreads();

    const int NIT = IN_F / GBK;   // 16
    for (int it = 0; it < NIT; it++) {
        const int cur = it & 1;
        float4 a_reg[2], b_reg[2];
        if (it + 1 < NIT) {
            const int k0 = (it + 1) * GBK;
#pragma unroll
            for (int i = 0; i < 2; i++) {
                int grow = row0 + ar0 + i * 64; if (grow >= N) grow = N - 1;
                a_reg[i] = *reinterpret_cast<const float4*>(x + (size_t)grow * IN_F + k0 + ac);
                b_reg[i] = *reinterpret_cast<const float4*>(W + (size_t)(k0 + br0 + i * 8) * GBN + bc);
            }
        }

#pragma unroll
        for (int ks = 0; ks < 2; ks++) {
            wmma::fragment<wmma::matrix_a, 16, 16, 8, wmma::precision::tf32, wmma::row_major> af[4];
#pragma unroll
            for (int mt = 0; mt < 4; mt++) {
                wmma::load_matrix_sync(af[mt], &As[cur][wm * 64 + mt * 16][ks * 8], GBK + 4);
#pragma unroll
                for (int t = 0; t < af[mt].num_elements; t++)
                    af[mt].x[t] = wmma::__float_to_tf32(af[mt].x[t]);
            }
#pragma unroll
            for (int nt = 0; nt < 2; nt++) {
                wmma::fragment<wmma::matrix_b, 16, 16, 8, wmma::precision::tf32, wmma::row_major> bf;
                wmma::load_matrix_sync(bf, &Bs[cur][ks * 8][wn * 32 + nt * 16], GBN);
#pragma unroll
                for (int t = 0; t < bf.num_elements; t++)
                    bf.x[t] = wmma::__float_to_tf32(bf.x[t]);
#pragma unroll
                for (int mt = 0; mt < 4; mt++)
                    wmma::mma_sync(acc[mt][nt], af[mt], bf, acc[mt][nt]);
            }
        }

        if (it + 1 < NIT) {
            const int nxt = 1 - cur;
#pragma unroll
            for (int i = 0; i < 2; i++) {
                *reinterpret_cast<float4*>(&As[nxt][ar0 + i * 64][ac]) = a_reg[i];
                *reinterpret_cast<float4*>(&Bs[nxt][br0 + i * 8][bc]) = b_reg[i];
            }
            __syncthreads();
        }
    }

    // ---- fused epilogue: acc -> smem stage -> fp16 hh + score partials ----
    __syncthreads();                               // done with As/Bs tiles
    float* wstage = &As[0][0][0] + wid * (16 * 20);   // 320 floats per warp

    const int r  = lane >> 1;          // 0..15 row within tile
    const int ch = (lane & 1) * 8;     // col half: 0 or 8

#pragma unroll
    for (int mt = 0; mt < 4; mt++) {
#pragma unroll
        for (int nt = 0; nt < 2; nt++) {
            wmma::store_matrix_sync(wstage, acc[mt][nt], 20, wmma::mem_row_major);
            __syncwarp();

            float v[8];
#pragma unroll
            for (int j = 0; j < 8; j++) v[j] = wstage[r * 20 + ch + j];

            const int grow = row0 + wm * 64 + mt * 16 + r;    // < N_PAD always
            const int gcol = wn * 32 + nt * 16 + ch;

            // fp16 store: 8 halves = one uint4
            __half2 hp[4];
#pragma unroll
            for (int j = 0; j < 4; j++) hp[j] = __floats2half2_rn(v[2 * j], v[2 * j + 1]);
            *reinterpret_cast<uint4*>(hh + (size_t)grow * OUT_F + gcol) =
                *reinterpret_cast<uint4*>(hp);

            // score partials (fp32)
            float p1 = 0.f, p2 = 0.f;
#pragma unroll
            for (int j = 0; j < 8; j++) {
                p1 = fmaf(v[j], a[gcol + j], p1);
                p2 = fmaf(v[j], a[OUT_F + gcol + j], p2);
            }
            p1 += __shfl_xor_sync(0xFFFFFFFFu, p1, 1);
            p2 += __shfl_xor_sync(0xFFFFFFFFu, p2, 1);
            if ((lane & 1) == 0) {
                atomicAdd(&ssrc[grow], p1);
                atomicAdd(&sdst[grow], p2);
            }
            __syncwarp();
        }
    }
}

// ---------------- CSR build: histogram --------------------------------------
__global__ __launch_bounds__(256) void hist_kernel(
    const int* __restrict__ src, int* __restrict__ deg, int E)
{
    const int e = blockIdx.x * blockDim.x + threadIdx.x;
    if (e < E) atomicAdd(&deg[src[e]], 1);
}

// ---------------- scan phase 1: per-block sums --------------------------------
__global__ __launch_bounds__(SCAN_BS) void scan1_kernel(
    const int* __restrict__ deg, int* __restrict__ part, int N)
{
    __shared__ int sh[SCAN_BS];
    const int idx = blockIdx.x * SCAN_BS + threadIdx.x;
    int v = (idx < N) ? deg[idx] : 0;
    sh[threadIdx.x] = v;
    __syncthreads();
#pragma unroll
    for (int o = SCAN_BS / 2; o > 0; o >>= 1) {
        if (threadIdx.x < o) sh[threadIdx.x] += sh[threadIdx.x + o];
        __syncthreads();
    }
    if (threadIdx.x == 0) part[blockIdx.x] = sh[0];
}

// ---------------- scan phase 2: exclusive scan of partials (1 block) ----------
__global__ __launch_bounds__(SCAN_BS) void scan2_kernel(int* __restrict__ part)
{
    __shared__ int sh[SCAN_BS];
    const int t = threadIdx.x;
    int v = (t < SCAN_NB) ? part[t] : 0;
    sh[t] = v;
    __syncthreads();
#pragma unroll
    for (int o = 1; o < SCAN_BS; o <<= 1) {
        int u = (t >= o) ? sh[t - o] : 0;
        __syncthreads();
        sh[t] += u;
        __syncthreads();
    }
    if (t < SCAN_NB) part[t] = sh[t] - v;
}

// ---------------- scan phase 3: local scan + write offsets --------------------
__global__ __launch_bounds__(SCAN_BS) void scan3_kernel(
    const int* __restrict__ deg, const int* __restrict__ part,
    int* __restrict__ off, int* __restrict__ cursor, int N, int E)
{
    __shared__ int sh[SCAN_BS];
    const int t = threadIdx.x;
    const int idx = blockIdx.x * SCAN_BS + t;
    int v = (idx < N) ? deg[idx] : 0;
    sh[t] = v;
    __syncthreads();
#pragma unroll
    for (int o = 1; o < SCAN_BS; o <<= 1) {
        int u = (t >= o) ? sh[t - o] : 0;
        __syncthreads();
        sh[t] += u;
        __syncthreads();
    }
    if (idx < N) {
        const int o = part[blockIdx.x] + sh[t] - v;
        off[idx] = o;
        cursor[idx] = o;
        if (idx == N - 1) off[N] = E;
    }
}

// ---------------- CSR build: scatter + edge weights (packed int2) -------------
__global__ __launch_bounds__(256) void scatter_kernel(
    const int* __restrict__ src, const int* __restrict__ dst,
    const float* __restrict__ ssrc, const float* __restrict__ sdst,
    int* __restrict__ cursor, int2* __restrict__ edge, int E)
{
    const int e = blockIdx.x * blockDim.x + threadIdx.x;
    if (e >= E) return;
    const int s = src[e];
    const int d = dst[e];
    const float sc = ssrc[s] + sdst[d];
    const float lr = sc >= 0.f ? sc : ALPHA * sc;
    const float w = __expf(-lr);
    const int pos = atomicAdd(&cursor[s], 1);
    edge[pos] = make_int2(d, __float_as_int(w));
}

// ---------------- aggregate: warp/node, double-buffered edges, fused elu ------
__global__ __launch_bounds__(256) void aggregate_kernel(
    const uint2* __restrict__ hh2, const int* __restrict__ off,
    const uint2* __restrict__ edge, float4* __restrict__ out4, int N)
{
    const int warp = (blockIdx.x * blockDim.x + threadIdx.x) >> 5;
    const int lane = threadIdx.x & 31;
    if (warp >= N) return;

    const int beg = off[warp];
    const int end = off[warp + 1];

    float ax = 0.f, ay = 0.f, az = 0.f, aw = 0.f, wsum = 0.f;

    const int nb = (end - beg) >> 3;       // full batches of 8
    uint2 eb[2][8];
    if (nb > 0) {
#pragma unroll
        for (int j = 0; j < 8; j++) eb[0][j] = edge[beg + j];
    }
    for (int b = 0; b < nb; b++) {
        const int cur = b & 1;
        if (b + 1 < nb) {
            const int base = beg + (b + 1) * 8;
#pragma unroll
            for (int j = 0; j < 8; j++) eb[1 - cur][j] = edge[base + j];
        }
        uint2 u[8];
#pragma unroll
        for (int j = 0; j < 8; j++) u[j] = hh2[(size_t)eb[cur][j].x * 32 + lane];
#pragma unroll
        for (int j = 0; j < 8; j++) {
            const float w = __int_as_float((int)eb[cur][j].y);
            float2 lo = __half22float2(*(const __half2*)&u[j].x);
            float2 hi = __half22float2(*(const __half2*)&u[j].y);
            ax = fmaf(w, lo.x, ax);
            ay = fmaf(w, lo.y, ay);
            az = fmaf(w, hi.x, az);
            aw = fmaf(w, hi.y, aw);
            wsum += w;
        }
    }
    for (int i = beg + nb * 8; i < end; i++) {
        const uint2 ed = edge[i];
        const float w = __int_as_float((int)ed.y);
        const uint2 u = hh2[(size_t)ed.x * 32 + lane];
        float2 lo = __half22float2(*(const __half2*)&u.x);
        float2 hi = __half22float2(*(const __half2*)&u.y);
        ax = fmaf(w, lo.x, ax);
        ay = fmaf(w, lo.y, ay);
        az = fmaf(w, hi.x, az);
        aw = fmaf(w, hi.y, aw);
        wsum += w;
    }

    const float r = 1.f / (wsum + EPSV);
    ax *= r; ay *= r; az *= r; aw *= r;
    ax = ax > 0.f ? ax : expm1f(ax);
    ay = ay > 0.f ? ay : expm1f(ay);
    az = az > 0.f ? az : expm1f(az);
    aw = aw > 0.f ? aw : expm1f(aw);
    out4[(size_t)warp * 32 + lane] = make_float4(ax, ay, az, aw);
}

// ---------------- launch ------------------------------------------------------
extern "C" void kernel_launch(void* const* d_in, const int* in_sizes, int n_in,
                              void* d_out, int out_size)
{
    const float* x  = (const float*)d_in[0];
    const int*   ei = (const int*)d_in[1];      // JAX x64 disabled -> int32
    const float* W  = (const float*)d_in[2];
    const float* a  = (const float*)d_in[3];
    float* out = (float*)d_out;

    const int N = in_sizes[0] / IN_F;        // 50000
    const int E = in_sizes[1] / 2;           // 1600000
    const int* src = ei;
    const int* dst = ei + E;

    float *ssrc, *sdst;
    __half* hh;
    int *deg, *off, *cursor, *part;
    int2* edge;
    cudaGetSymbolAddress((void**)&hh,     g_hh);
    cudaGetSymbolAddress((void**)&ssrc,   g_ssrc);
    cudaGetSymbolAddress((void**)&sdst,   g_sdst);
    cudaGetSymbolAddress((void**)&deg,    g_deg);
    cudaGetSymbolAddress((void**)&off,    g_off);
    cudaGetSymbolAddress((void**)&cursor, g_cursor);
    cudaGetSymbolAddress((void**)&part,   g_part);
    cudaGetSymbolAddress((void**)&edge,   g_edge);

    cudaMemsetAsync(deg,  0, (size_t)N_NODES * sizeof(int), 0);
    cudaMemsetAsync(ssrc, 0, (size_t)N_PAD * sizeof(float), 0);
    cudaMemsetAsync(sdst, 0, (size_t)N_PAD * sizeof(float), 0);

    // CSR histogram
    hist_kernel<<<(E + 255) / 256, 256>>>(src, deg, E);

    // 3-phase parallel exclusive scan
    scan1_kernel<<<SCAN_NB, SCAN_BS>>>(deg, part, N);
    scan2_kernel<<<1, SCAN_BS>>>(part);
    scan3_kernel<<<SCAN_NB, SCAN_BS>>>(deg, part, off, cursor, N, E);

    // fused: h = x @ W (tf32), fp16 h store, per-node scores
    gemm_tf32_fused_kernel<<<(N + GBM - 1) / GBM, 256>>>(x, W, a, hh, ssrc, sdst, N);

    // scatter edges into CSR order + precompute weights (packed)
    scatter_kernel<<<(E + 255) / 256, 256>>>(src, dst, ssrc, sdst, cursor, edge, E);

    // aggregate per node (atomic-free, fp16 gather, double-buffered) + fused elu
    aggregate_kernel<<<(N * 32 + 255) / 256, 256>>>(
        (const uint2*)hh, off, (const uint2*)edge, (float4*)out, N);
}